// round 14
// baseline (speedup 1.0000x reference)
#include <cuda_runtime.h>

// Inputs (metadata order):
// 0: y (B,4N) f32 | 1: Ic (B,) | 2: C (N,) | 3: g_Na | 4: E_Na | 5: g_K | 6: E_K
// 7: g_L | 8: E_L | 9: m_inf | 10: tau_m | 11: h_inf | 12: tau_h | 13: n_inf
// 14: tau_n | 15: g_C (N,N)
// Output: ydot (B,4N) followed by J (B,4N,4N), f32.

#define BATCH 256
#define NN    128   // N
#define E4    512   // 4*N
#define BPB   4     // batches per ydot block

// per-(b,i) diagonal V-row tuple (JVV_diag, JVm, JVh, JVn)
__device__ float4 g_diag[BATCH * NN];

// ---------------------------------------------------------------------------
// streaming 128-bit store (evict-first: J is write-once)
// ---------------------------------------------------------------------------
__device__ __forceinline__ void stg_cs(float4* p, float4 v) {
    asm volatile("st.global.cs.v4.f32 [%0], {%1, %2, %3, %4};"
                 :: "l"(p), "f"(v.x), "f"(v.y), "f"(v.z), "f"(v.w)
                 : "memory");
}

// ===========================================================================
// Kernel A (side stream, concurrent): ydot + g_diag.  Touches out_ydot and
// g_diag only -> fully independent of kernel B.
// grid = BATCH/BPB = 64 blocks, 128 threads.
// ===========================================================================
__global__ void ydot_kernel(
    const float* __restrict__ y, const float* __restrict__ Ic,
    const float* __restrict__ C,
    const float* __restrict__ gNa, const float* __restrict__ ENa,
    const float* __restrict__ gK,  const float* __restrict__ EK,
    const float* __restrict__ gL,  const float* __restrict__ EL,
    const float* __restrict__ minf, const float* __restrict__ taum,
    const float* __restrict__ hinf, const float* __restrict__ tauh,
    const float* __restrict__ ninf, const float* __restrict__ taun,
    const float* __restrict__ gC,
    float* __restrict__ out_ydot)
{
    __shared__ float Gt[NN][33];       // padded gC column tile
    __shared__ float Wj[NN];           // invC[j]
    __shared__ float WVs[BPB][NN];     // invC[j] * V_b[j]
    __shared__ float red[4];

    int b0 = blockIdx.x * BPB;
    int i  = threadIdx.x;
    int lane = i & 31;
    int w    = i >> 5;

    float invCi = 1.0f / C[i];
    Wj[i] = invCi;

    float V[BPB], m[BPB], h[BPB], n[BPB];
    #pragma unroll
    for (int bb = 0; bb < BPB; bb++) {
        float4 y4 = reinterpret_cast<const float4*>(y)[(b0 + bb) * NN + i];
        V[bb] = y4.x; m[bb] = y4.y; h[bb] = y4.z; n[bb] = y4.w;
        WVs[bb][i] = invCi * y4.x;
    }
    __syncthreads();

    float rs = 0.0f;                   // sum_j g[i][j] * invC[j]  (batch-indep)
    float gv[BPB] = {0.f, 0.f, 0.f, 0.f};

    #pragma unroll
    for (int t = 0; t < 4; t++) {
        #pragma unroll 8
        for (int k = 0; k < 32; k++) {
            int row = k * 4 + w;
            Gt[row][lane] = gC[row * NN + t * 32 + lane];
        }
        __syncthreads();

        #pragma unroll 4
        for (int jj = 0; jj < 32; jj++) {
            float g = Gt[i][jj];
            int j = t * 32 + jj;
            rs += g * Wj[j];
            #pragma unroll
            for (int bb = 0; bb < BPB; bb++)
                gv[bb] += g * WVs[bb][j];
        }
        __syncthreads();
    }

    // block-reduce rs -> S (deterministic tree), broadcast through smem
    float tr = rs;
    #pragma unroll
    for (int o2 = 16; o2 > 0; o2 >>= 1)
        tr += __shfl_xor_sync(0xFFFFFFFFu, tr, o2);
    if (lane == 0) red[w] = tr;
    __syncthreads();
    float S = red[0] + red[1] + red[2] + red[3];

    float ga = gNa[i], gk = gK[i], gl = gL[i];
    float eNa = ENa[i], eK = EK[i], eL = EL[i];
    float mi = minf[i], hi = hinf[i], ni = ninf[i];
    float itm = 1.0f / taum[i], ith = 1.0f / tauh[i], itn = 1.0f / taun[i];
    float gdiag = gC[i * NN + i];

    #pragma unroll
    for (int bb = 0; bb < BPB; bb++) {
        int b = b0 + bb;
        float Vb = V[bb], mb = m[bb], hb = h[bb], nb = n[bb];
        float acc = Vb * rs - gv[bb];
        float m2 = mb * mb, m3 = m2 * mb;
        float n2 = nb * nb, n3 = n2 * nb, n4 = n3 * nb;
        float dNa = Vb - eNa, dK = Vb - eK;

        float Vdot = invCi * (-ga * m3 * hb * dNa
                              - gk * n4 * dK
                              - gl * (Vb - eL)
                              + Ic[b]) + acc;
        float4 o;
        o.x = Vdot;
        o.y = (mi - mb) * itm;
        o.z = (hi - hb) * ith;
        o.w = (ni - nb) * itn;
        reinterpret_cast<float4*>(out_ydot)[b * NN + i] = o;

        // V-row diagonal tuple (full value, including the -gC[i,i]/C[i] term
        // that the background fill also writes; scatter OVERWRITES, not adds)
        float4 dv;
        dv.x = -gdiag * invCi + S + invCi * (-gl - ga * hb * m3 - gk * n4);
        dv.y = -invCi * (3.0f * ga * hb * m2 * dNa);
        dv.z = -invCi * (ga * m3 * dNa);
        dv.w = -invCi * (4.0f * gk * n3 * dK);
        g_diag[b * NN + i] = dv;
    }
}

// ===========================================================================
// Kernel B (main stream): BRANCH-FREE background fill of ALL of J.
// Every float4 written unconditionally (diagonals get background values,
// overwritten later by diag_scatter).  Loads hoisted ahead of all stores.
// float4-idx layout: j = idx & 127; r = (idx>>7) & 511; b = idx>>16.
// Per thread: rows r0, r0+2, r0+4, r0+6 at fixed j.
// ===========================================================================
__global__ void __launch_bounds__(256) jfill_kernel(
    const float* __restrict__ C,
    const float* __restrict__ gC,
    float* __restrict__ J)
{
    int base = blockIdx.x * 1024 + threadIdx.x;
    int j = base & (NN - 1);
    float invCj = 1.0f / C[j];

    // hoisted (predicated) loads: rt==0 rows need gC[i,j]; others get 0.
    float gval[4];
    #pragma unroll
    for (int k = 0; k < 4; k++) {
        int r  = ((base >> 7) + 2 * k) & (E4 - 1);
        int rt = r & 3;                    // warp-uniform
        int i  = r >> 2;
        gval[k] = (rt == 0) ? gC[i * NN + j] : 0.0f;
    }

    float4* out = reinterpret_cast<float4*>(J);
    #pragma unroll
    for (int k = 0; k < 4; k++) {
        stg_cs(out + base + k * 256,
               make_float4(-gval[k] * invCj, 0.f, 0.f, 0.f));
    }
}

// ===========================================================================
// Kernel C (after join): overwrite the 4 diagonal float4s per (b,i).
// 32768 threads; 8 MB of scattered 16B stores (~2us).
// ===========================================================================
__global__ void diag_scatter(
    const float* __restrict__ taum, const float* __restrict__ tauh,
    const float* __restrict__ taun,
    float* __restrict__ J)
{
    int t = blockIdx.x * 256 + threadIdx.x;   // t in [0, BATCH*NN)
    int i = t & (NN - 1);
    int b = t >> 7;

    float4 dv = g_diag[t];
    float itm = 1.0f / taum[i];
    float ith = 1.0f / tauh[i];
    float itn = 1.0f / taun[i];

    float4* outJ4 = reinterpret_cast<float4*>(J);
    int idx0 = b * (E4 * NN) + (4 * i) * NN + i;      // V row, col-quad i
    outJ4[idx0]          = dv;
    outJ4[idx0 + NN]     = make_float4(0.f, -itm, 0.f, 0.f);  // m row
    outJ4[idx0 + 2*NN]   = make_float4(0.f, 0.f, -ith, 0.f);  // h row
    outJ4[idx0 + 3*NN]   = make_float4(0.f, 0.f, 0.f, -itn);  // n row
}

// ---------------------------------------------------------------------------
// Fork/join: ydot on a side stream (concurrent with jfill), then scatter.
// Host-side stream/event creation is one-time init; no device memory.
// ---------------------------------------------------------------------------
static cudaStream_t g_s2  = nullptr;
static cudaEvent_t  g_ev1 = nullptr;
static cudaEvent_t  g_ev2 = nullptr;

extern "C" void kernel_launch(void* const* d_in, const int* in_sizes, int n_in,
                              void* d_out, int out_size) {
    const float* y    = (const float*)d_in[0];
    const float* Ic   = (const float*)d_in[1];
    const float* C    = (const float*)d_in[2];
    const float* gNa  = (const float*)d_in[3];
    const float* ENa  = (const float*)d_in[4];
    const float* gK   = (const float*)d_in[5];
    const float* EK   = (const float*)d_in[6];
    const float* gL   = (const float*)d_in[7];
    const float* EL   = (const float*)d_in[8];
    const float* minf = (const float*)d_in[9];
    const float* taum = (const float*)d_in[10];
    const float* hinf = (const float*)d_in[11];
    const float* tauh = (const float*)d_in[12];
    const float* ninf = (const float*)d_in[13];
    const float* taun = (const float*)d_in[14];
    const float* gC   = (const float*)d_in[15];

    float* out_ydot = (float*)d_out;
    float* out_J    = out_ydot + BATCH * E4;

    if (!g_s2) {
        cudaStreamCreateWithFlags(&g_s2, cudaStreamNonBlocking);
        cudaEventCreateWithFlags(&g_ev1, cudaEventDisableTiming);
        cudaEventCreateWithFlags(&g_ev2, cudaEventDisableTiming);
    }

    // fork
    cudaEventRecord(g_ev1, 0);
    cudaStreamWaitEvent(g_s2, g_ev1, 0);

    // branch 1 (side stream): ydot + g_diag (~6us, hidden under jfill)
    ydot_kernel<<<BATCH / BPB, NN, 0, g_s2>>>(
        y, Ic, C, gNa, ENa, gK, EK, gL, EL,
        minf, taum, hinf, tauh, ninf, taun, gC, out_ydot);

    // branch 2 (main stream): branch-free background fill of ALL of J (~39us)
    const int total4 = BATCH * E4 * NN;   // 16,777,216 float4
    jfill_kernel<<<total4 / 1024, 256>>>(C, gC, out_J);

    // join: scatter must see both jfill (same stream) and ydot (event)
    cudaEventRecord(g_ev2, g_s2);
    cudaStreamWaitEvent(0, g_ev2, 0);

    diag_scatter<<<(BATCH * NN) / 256, 256>>>(taum, tauh, taun, out_J);
}

// round 15
// speedup vs baseline: 1.1201x; 1.1201x over previous
#include <cuda_runtime.h>

// Inputs (metadata order):
// 0: y (B,4N) f32 | 1: Ic (B,) | 2: C (N,) | 3: g_Na | 4: E_Na | 5: g_K | 6: E_K
// 7: g_L | 8: E_L | 9: m_inf | 10: tau_m | 11: h_inf | 12: tau_h | 13: n_inf
// 14: tau_n | 15: g_C (N,N)
// Output: ydot (B,4N) followed by J (B,4N,4N), f32.

#define BATCH 256
#define NN    128   // N
#define E4    512   // 4*N
#define NCHUNK 4    // j-chunks for split-K coupling matvec

// scratch: per-(b,chunk,i) partial gv; per-(chunk,i) partial rs; per-(b,i) diag
__device__ float  g_pgv[BATCH * NCHUNK * NN];   // 512 KB
__device__ float  g_prs[NCHUNK * NN];           // 2 KB
__device__ float4 g_diag[BATCH * NN];           // 512 KB

// ---------------------------------------------------------------------------
// streaming 128-bit store (evict-first: J is write-once)
// ---------------------------------------------------------------------------
__device__ __forceinline__ void stg_cs(float4* p, float4 v) {
    asm volatile("st.global.cs.v4.f32 [%0], {%1, %2, %3, %4};"
                 :: "l"(p), "f"(v.x), "f"(v.y), "f"(v.z), "f"(v.w)
                 : "memory");
}

// ===========================================================================
// Kernel P: split-K partials of the coupling matvec.
// grid = BATCH*NCHUNK = 1024 blocks, 128 threads (thread = row i).
// Block (b, chunk) stages gC[:, 32c..32c+32) (16 KB, fully coalesced) and
// computes pgv[i] = sum_jj g[i][jj]*invC*V_b, prs[i] = sum_jj g[i][jj]*invC.
// 1024 blocks ~ 7/SM -> latency-bound matvec becomes throughput-bound.
// ===========================================================================
__global__ void partial_kernel(
    const float* __restrict__ y,
    const float* __restrict__ C,
    const float* __restrict__ gC)
{
    __shared__ float Gt[NN][33];   // 128 rows x 32 cols (padded)
    __shared__ float Wc[32];       // invC[j]
    __shared__ float Wv[32];       // invC[j] * V_b[j]

    int chunk = blockIdx.x & (NCHUNK - 1);
    int b     = blockIdx.x >> 2;
    int i     = threadIdx.x;
    int lane  = i & 31;
    int w     = i >> 5;            // warp 0..3
    int j0    = chunk * 32;

    // warp w stages rows [32w, 32w+32), cols [j0, j0+32): coalesced 128B rows
    #pragma unroll 8
    for (int r = 0; r < 32; r++)
        Gt[w * 32 + r][lane] = gC[(w * 32 + r) * NN + j0 + lane];

    if (i < 32) {
        float ic = 1.0f / C[j0 + i];
        Wc[i] = ic;
        Wv[i] = ic * y[b * E4 + 4 * (j0 + i)];   // V component
    }
    __syncthreads();

    float pgv = 0.f, prs = 0.f;
    #pragma unroll
    for (int jj = 0; jj < 32; jj++) {
        float g = Gt[i][jj];
        prs += g * Wc[jj];
        pgv += g * Wv[jj];
    }

    g_pgv[(b * NCHUNK + chunk) * NN + i] = pgv;
    if (b == 0) g_prs[chunk * NN + i] = prs;     // batch-independent
}

// ===========================================================================
// Kernel F: combine partials -> ydot output + g_diag.
// grid = BATCH blocks, 128 threads (thread = neuron i).
// ===========================================================================
__global__ void final_kernel(
    const float* __restrict__ y, const float* __restrict__ Ic,
    const float* __restrict__ C,
    const float* __restrict__ gNa, const float* __restrict__ ENa,
    const float* __restrict__ gK,  const float* __restrict__ EK,
    const float* __restrict__ gL,  const float* __restrict__ EL,
    const float* __restrict__ minf, const float* __restrict__ taum,
    const float* __restrict__ hinf, const float* __restrict__ tauh,
    const float* __restrict__ ninf, const float* __restrict__ taun,
    float* __restrict__ out_ydot)
{
    __shared__ float red[4];

    int b = blockIdx.x;
    int i = threadIdx.x;
    int lane = i & 31;
    int w    = i >> 5;

    float rs = g_prs[0 * NN + i] + g_prs[1 * NN + i]
             + g_prs[2 * NN + i] + g_prs[3 * NN + i];
    const float* pg = g_pgv + b * NCHUNK * NN + i;
    float gv = pg[0] + pg[NN] + pg[2 * NN] + pg[3 * NN];

    // block-reduce rs -> S (deterministic tree, identical per block)
    float tr = rs;
    #pragma unroll
    for (int o2 = 16; o2 > 0; o2 >>= 1)
        tr += __shfl_xor_sync(0xFFFFFFFFu, tr, o2);
    if (lane == 0) red[w] = tr;
    __syncthreads();
    float S = red[0] + red[1] + red[2] + red[3];

    float4 y4 = reinterpret_cast<const float4*>(y)[b * NN + i];
    float V = y4.x, m = y4.y, h = y4.z, n = y4.w;
    float invCi = 1.0f / C[i];

    float m2 = m * m, m3 = m2 * m;
    float n2 = n * n, n3 = n2 * n, n4 = n3 * n;
    float ga = gNa[i], gk = gK[i], gl = gL[i];
    float dNa = V - ENa[i], dK = V - EK[i];

    float acc  = V * rs - gv;
    float Vdot = invCi * (-ga * m3 * h * dNa
                          - gk * n4 * dK
                          - gl * (V - EL[i])
                          + Ic[b]) + acc;
    float4 o;
    o.x = Vdot;
    o.y = (minf[i] - m) / taum[i];
    o.z = (hinf[i] - h) / tauh[i];
    o.w = (ninf[i] - n) / taun[i];
    reinterpret_cast<float4*>(out_ydot)[b * NN + i] = o;

    // diagonal V-row tuple; jfill adds the -gC[i,i]/C[i] background itself
    float4 d;
    d.x = S + invCi * (-gl - ga * h * m3 - gk * n4);
    d.y = -invCi * (3.0f * ga * h * m2 * dNa);
    d.z = -invCi * (ga * m3 * dNa);
    d.w = -invCi * (4.0f * gk * n3 * dK);
    g_diag[b * NN + i] = d;
}

// ===========================================================================
// Kernel J: fill J — EXACT R8 structure (proven 39.0us / DRAM 67.8%).
// 4 float4s per thread, stride-256 interleave, unconditional .cs stores,
// diag merged by value predicate only.
// float4-idx layout: j = idx & 127; r = (idx>>7) & 511; b = idx>>16.
// ===========================================================================
__global__ void __launch_bounds__(256) jfill_kernel(
    const float* __restrict__ C,
    const float* __restrict__ taum, const float* __restrict__ tauh,
    const float* __restrict__ taun,
    const float* __restrict__ gC,
    float* __restrict__ J)
{
    int base = blockIdx.x * 1024 + threadIdx.x;
    int j = base & (NN - 1);
    float invCj = 1.0f / C[j];

    float4* out = reinterpret_cast<float4*>(J);

    #pragma unroll
    for (int k = 0; k < 4; k++) {
        int idx = base + k * 256;
        int r = (idx >> 7) & (E4 - 1);
        int b = idx >> 16;
        int rt = r & 3;      // warp-uniform
        int i  = r >> 2;

        float4 v = make_float4(0.f, 0.f, 0.f, 0.f);

        if (rt == 0) {
            v.x = -gC[i * NN + j] * invCj;
            if (i == j) {
                float4 d = g_diag[b * NN + i];
                v.x += d.x; v.y = d.y; v.z = d.z; v.w = d.w;
            }
        } else if (i == j) {
            float tt = (rt == 1) ? taum[i] : (rt == 2) ? tauh[i] : taun[i];
            float val = -1.0f / tt;
            if (rt == 1) v.y = val;
            else if (rt == 2) v.z = val;
            else v.w = val;
        }

        stg_cs(out + idx, v);
    }
}

// ---------------------------------------------------------------------------
extern "C" void kernel_launch(void* const* d_in, const int* in_sizes, int n_in,
                              void* d_out, int out_size) {
    const float* y    = (const float*)d_in[0];
    const float* Ic   = (const float*)d_in[1];
    const float* C    = (const float*)d_in[2];
    const float* gNa  = (const float*)d_in[3];
    const float* ENa  = (const float*)d_in[4];
    const float* gK   = (const float*)d_in[5];
    const float* EK   = (const float*)d_in[6];
    const float* gL   = (const float*)d_in[7];
    const float* EL   = (const float*)d_in[8];
    const float* minf = (const float*)d_in[9];
    const float* taum = (const float*)d_in[10];
    const float* hinf = (const float*)d_in[11];
    const float* tauh = (const float*)d_in[12];
    const float* ninf = (const float*)d_in[13];
    const float* taun = (const float*)d_in[14];
    const float* gC   = (const float*)d_in[15];

    float* out_ydot = (float*)d_out;
    float* out_J    = out_ydot + BATCH * E4;

    partial_kernel<<<BATCH * NCHUNK, NN>>>(y, C, gC);
    final_kernel<<<BATCH, NN>>>(y, Ic, C, gNa, ENa, gK, EK, gL, EL,
                                minf, taum, hinf, tauh, ninf, taun, out_ydot);
    const int total4 = BATCH * E4 * NN;   // 16,777,216 float4
    jfill_kernel<<<total4 / 1024, 256>>>(C, taum, tauh, taun, gC, out_J);
}